// round 1
// baseline (speedup 1.0000x reference)
#include <cuda_runtime.h>

typedef unsigned long long ull;

#define HF 128
#define HV 32           // float4 per feature row
#define NMAX 50016
#define EMAX 800032

// ---------------- scratch (static device memory; no allocation) ----------------
__device__ float g_hn[NMAX * HF];        // relu(BN(x))
__device__ float g_u [NMAX * HF];        // agg + hn  (MLP input)
__device__ float g_y1[NMAX * 2 * HF];    // GEMM1 output (pre-LN)
__device__ int   g_deg[NMAX];
__device__ int   g_rs [NMAX + 1];
__device__ int   g_cur[NMAX];
__device__ int   g_ssrc[EMAX];
__device__ int   g_seid[EMAX];

// ---------------- f32x2 helpers ----------------
__device__ __forceinline__ ull pk(float a, float b) {
    ull r; asm("mov.b64 %0, {%1, %2};" : "=l"(r) : "f"(a), "f"(b)); return r;
}
__device__ __forceinline__ float2 upk(ull v) {
    float2 r; asm("mov.b64 {%0, %1}, %2;" : "=f"(r.x), "=f"(r.y) : "l"(v)); return r;
}
__device__ __forceinline__ ull f2fma(ull a, ull b, ull c) {
    ull d; asm("fma.rn.f32x2 %0, %1, %2, %3;" : "=l"(d) : "l"(a), "l"(b), "l"(c)); return d;
}

// ---------------- K0: hn = relu(BN(h)); also zero deg ----------------
__global__ void k_hn(const float4* __restrict__ h,
                     const float4* __restrict__ bw, const float4* __restrict__ bb,
                     const float4* __restrict__ bm, const float4* __restrict__ bv,
                     int n)
{
    int i = blockIdx.x * blockDim.x + threadIdx.x;
    if (i < n) g_deg[i] = 0;
    if (i >= n * HV) return;
    int j = i & (HV - 1);
    float4 x = h[i];
    float4 w = bw[j], b = bb[j], m = bm[j], v = bv[j];
    float4 o;
    o.x = fmaxf((x.x - m.x) * rsqrtf(v.x + 1e-5f) * w.x + b.x, 0.f);
    o.y = fmaxf((x.y - m.y) * rsqrtf(v.y + 1e-5f) * w.y + b.y, 0.f);
    o.z = fmaxf((x.z - m.z) * rsqrtf(v.z + 1e-5f) * w.z + b.z, 0.f);
    o.w = fmaxf((x.w - m.w) * rsqrtf(v.w + 1e-5f) * w.w + b.w, 0.f);
    ((float4*)g_hn)[i] = o;
}

// ---------------- K1: degree histogram ----------------
__global__ void k_hist(const int* __restrict__ dst, int e)
{
    int i = blockIdx.x * blockDim.x + threadIdx.x;
    if (i < e) atomicAdd(&g_deg[dst[i]], 1);
}

// ---------------- K2: exclusive scan over deg (single block) ----------------
__global__ void k_scan(int n)
{
    __shared__ int warp_sums[32];
    int tid = threadIdx.x;
    int chunk = (n + 1023) / 1024;
    int b = tid * chunk;
    int e = min(b + chunk, n);
    int s = 0;
    for (int i = b; i < e; ++i) s += g_deg[i];
    int lane = tid & 31, wid = tid >> 5;
    int v = s;
    #pragma unroll
    for (int o = 1; o < 32; o <<= 1) {
        int u = __shfl_up_sync(0xffffffffu, v, o);
        if (lane >= o) v += u;
    }
    if (lane == 31) warp_sums[wid] = v;
    __syncthreads();
    if (wid == 0) {
        int w = warp_sums[lane];
        #pragma unroll
        for (int o = 1; o < 32; o <<= 1) {
            int u = __shfl_up_sync(0xffffffffu, w, o);
            if (lane >= o) w += u;
        }
        warp_sums[lane] = w;
    }
    __syncthreads();
    int incl = v + (wid > 0 ? warp_sums[wid - 1] : 0);
    int run = incl - s;           // exclusive
    for (int i = b; i < e; ++i) {
        g_rs[i] = run; g_cur[i] = run;
        run += g_deg[i];
    }
    if (tid == 0) g_rs[n] = warp_sums[31];
}

// ---------------- K3: scatter edges by dst ----------------
__global__ void k_scatter(const int* __restrict__ src, const int* __restrict__ dst, int e)
{
    int i = blockIdx.x * blockDim.x + threadIdx.x;
    if (i >= e) return;
    int d = dst[i];
    int p = atomicAdd(&g_cur[d], 1);
    g_ssrc[p] = src[i];
    g_seid[p] = i;
}

// ---------------- K4: one-pass softmax aggregation (warp per dst node) ----------------
__global__ void k_agg(const float4* __restrict__ ea, const float* __restrict__ tp, int n)
{
    int warp = (blockIdx.x * blockDim.x + threadIdx.x) >> 5;
    int lane = threadIdx.x & 31;
    if (warp >= n) return;
    float t = *tp;
    int s0 = g_rs[warp], s1 = g_rs[warp + 1];
    const float4* hn4 = (const float4*)g_hn;
    float4 S = make_float4(0.f, 0.f, 0.f, 0.f);
    float4 P = make_float4(0.f, 0.f, 0.f, 0.f);
    for (int base = s0; base < s1; base += 32) {
        int i = base + lane;
        int ms = 0, me = 0;
        if (i < s1) { ms = g_ssrc[i]; me = g_seid[i]; }
        int cnt = min(32, s1 - base);
        for (int j = 0; j < cnt; ++j) {
            int sj = __shfl_sync(0xffffffffu, ms, j);
            int ej = __shfl_sync(0xffffffffu, me, j);
            float4 a  = ea[ej * HV + lane];
            float4 hv = hn4[sj * HV + lane];
            float m0 = fmaxf(a.x + hv.x, 0.f) + 1e-7f; float e0 = __expf(m0 * t);
            float m1 = fmaxf(a.y + hv.y, 0.f) + 1e-7f; float e1 = __expf(m1 * t);
            float m2 = fmaxf(a.z + hv.z, 0.f) + 1e-7f; float e2 = __expf(m2 * t);
            float m3 = fmaxf(a.w + hv.w, 0.f) + 1e-7f; float e3 = __expf(m3 * t);
            S.x += e0; P.x = fmaf(m0, e0, P.x);
            S.y += e1; P.y = fmaf(m1, e1, P.y);
            S.z += e2; P.z = fmaf(m2, e2, P.z);
            S.w += e3; P.w = fmaf(m3, e3, P.w);
        }
    }
    float4 hd = hn4[warp * HV + lane];
    float4 u;
    u.x = P.x / (S.x + 1e-16f) + hd.x;
    u.y = P.y / (S.y + 1e-16f) + hd.y;
    u.z = P.z / (S.z + 1e-16f) + hd.z;
    u.w = P.w / (S.w + 1e-16f) + hd.w;
    ((float4*)g_u)[warp * HV + lane] = u;
}

// ---------------- K5: GEMM1  y1 = u @ W1 + b1   (64 rows/block, FFMA2) ----------------
#define SMEM1 ((128 * 256 + 128 * 64) * 4)
__global__ void __launch_bounds__(256) k_gemm1(const float* __restrict__ W1,
                                               const float* __restrict__ b1, int n)
{
    extern __shared__ float sm[];
    float* Ws = sm;               // [128][256]
    float* Ut = sm + 128 * 256;   // [128][64] k-major
    int tid = threadIdx.x;
    int row0 = blockIdx.x * 64;

    for (int i = tid; i < (128 * 256) / 4; i += 256)
        ((float4*)Ws)[i] = ((const float4*)W1)[i];

    const float4* U4 = (const float4*)g_u;
    for (int i = tid; i < 64 * 32; i += 256) {
        int r = i >> 5, j = i & 31;
        float4 v = (row0 + r < n) ? U4[(row0 + r) * 32 + j] : make_float4(0.f, 0.f, 0.f, 0.f);
        int k = 4 * j;
        Ut[(k + 0) * 64 + r] = v.x;
        Ut[(k + 1) * 64 + r] = v.y;
        Ut[(k + 2) * 64 + r] = v.z;
        Ut[(k + 3) * 64 + r] = v.w;
    }
    __syncthreads();

    int rg = tid & 15, cg = tid >> 4;
    int r0 = rg * 4, c0 = cg * 16;
    ull acc[4][8];
    #pragma unroll
    for (int a = 0; a < 4; ++a)
        #pragma unroll
        for (int p = 0; p < 8; ++p) acc[a][p] = 0ull;

    for (int k = 0; k < 128; ++k) {
        float4 xv = *(const float4*)(Ut + k * 64 + r0);
        ull x0 = pk(xv.x, xv.x), x1 = pk(xv.y, xv.y);
        ull x2 = pk(xv.z, xv.z), x3 = pk(xv.w, xv.w);
        const ull* wr = (const ull*)(Ws + k * 256 + c0);
        #pragma unroll
        for (int p = 0; p < 8; ++p) {
            ull wv = wr[p];
            acc[0][p] = f2fma(x0, wv, acc[0][p]);
            acc[1][p] = f2fma(x1, wv, acc[1][p]);
            acc[2][p] = f2fma(x2, wv, acc[2][p]);
            acc[3][p] = f2fma(x3, wv, acc[3][p]);
        }
    }

    const float2* b12 = (const float2*)b1;
    #pragma unroll
    for (int rr = 0; rr < 4; ++rr) {
        int row = row0 + r0 + rr;
        if (row >= n) break;
        float2* out = (float2*)(g_y1 + (size_t)row * 256 + c0);
        #pragma unroll
        for (int p = 0; p < 8; ++p) {
            float2 v = upk(acc[rr][p]);
            float2 bb = b12[c0 / 2 + p];
            v.x += bb.x; v.y += bb.y;
            out[p] = v;
        }
    }
}

// ---------------- K6: LN + relu + GEMM2 + bias + residual ----------------
#define SMEM2 ((256 * 128 + 256 * 64) * 4)
__global__ void __launch_bounds__(256) k_gemm2(const float* __restrict__ W2,
                                               const float* __restrict__ b2,
                                               const float* __restrict__ lnw,
                                               const float* __restrict__ lnb,
                                               const float4* __restrict__ h,
                                               float4* __restrict__ out, int n)
{
    extern __shared__ float sm[];
    float* Ws = sm;               // [256][128]
    float* Yt = sm + 256 * 128;   // [256][64] k-major
    __shared__ float s_lnw[256], s_lnb[256];
    __shared__ float s_red[256], s_red2[256];
    __shared__ float s_mean[64], s_scale[64];
    int tid = threadIdx.x;
    int row0 = blockIdx.x * 64;

    for (int i = tid; i < (256 * 128) / 4; i += 256)
        ((float4*)Ws)[i] = ((const float4*)W2)[i];
    s_lnw[tid] = lnw[tid];
    s_lnb[tid] = lnb[tid];

    const float4* Y4 = (const float4*)g_y1;
    for (int i = tid; i < 64 * 64; i += 256) {
        int r = i >> 6, j = i & 63;
        float4 v = (row0 + r < n) ? Y4[(size_t)(row0 + r) * 64 + j] : make_float4(0.f, 0.f, 0.f, 0.f);
        int k = 4 * j;
        Yt[(k + 0) * 64 + r] = v.x;
        Yt[(k + 1) * 64 + r] = v.y;
        Yt[(k + 2) * 64 + r] = v.z;
        Yt[(k + 3) * 64 + r] = v.w;
    }
    __syncthreads();

    {   // LayerNorm stats (4 partial reducers per row)
        int r = tid & 63, part = tid >> 6;
        float s = 0.f, s2 = 0.f;
        for (int k = part * 64; k < part * 64 + 64; ++k) {
            float v = Yt[k * 64 + r];
            s += v; s2 = fmaf(v, v, s2);
        }
        s_red[tid] = s; s_red2[tid] = s2;
    }
    __syncthreads();
    if (tid < 64) {
        float s  = s_red[tid]  + s_red[64 + tid]  + s_red[128 + tid]  + s_red[192 + tid];
        float s2 = s_red2[tid] + s_red2[64 + tid] + s_red2[128 + tid] + s_red2[192 + tid];
        float mean = s * (1.f / 256.f);
        float var = fmaxf(s2 * (1.f / 256.f) - mean * mean, 0.f);
        s_mean[tid] = mean;
        s_scale[tid] = rsqrtf(var + 1e-5f);
    }
    __syncthreads();
    for (int i = tid; i < 256 * 64; i += 256) {
        int k = i >> 6, r = i & 63;
        float v = (Yt[i] - s_mean[r]) * s_scale[r] * s_lnw[k] + s_lnb[k];
        Yt[i] = fmaxf(v, 0.f);
    }
    __syncthreads();

    int rg = tid & 15, cg = tid >> 4;
    int r0 = rg * 4, c0 = cg * 8;
    ull acc[4][4];
    #pragma unroll
    for (int a = 0; a < 4; ++a)
        #pragma unroll
        for (int p = 0; p < 4; ++p) acc[a][p] = 0ull;

    for (int k = 0; k < 256; ++k) {
        float4 xv = *(const float4*)(Yt + k * 64 + r0);
        ull x0 = pk(xv.x, xv.x), x1 = pk(xv.y, xv.y);
        ull x2 = pk(xv.z, xv.z), x3 = pk(xv.w, xv.w);
        const ull* wr = (const ull*)(Ws + k * 128 + c0);
        #pragma unroll
        for (int p = 0; p < 4; ++p) {
            ull wv = wr[p];
            acc[0][p] = f2fma(x0, wv, acc[0][p]);
            acc[1][p] = f2fma(x1, wv, acc[1][p]);
            acc[2][p] = f2fma(x2, wv, acc[2][p]);
            acc[3][p] = f2fma(x3, wv, acc[3][p]);
        }
    }

    const float2* b22 = (const float2*)b2;
    #pragma unroll
    for (int rr = 0; rr < 4; ++rr) {
        int row = row0 + r0 + rr;
        if (row >= n) break;
        float2 v0 = upk(acc[rr][0]), v1 = upk(acc[rr][1]);
        float2 v2 = upk(acc[rr][2]), v3 = upk(acc[rr][3]);
        float2 bb0 = b22[c0 / 2 + 0], bb1 = b22[c0 / 2 + 1];
        float2 bb2 = b22[c0 / 2 + 2], bb3 = b22[c0 / 2 + 3];
        float4 h0 = h[row * 32 + c0 / 4 + 0];
        float4 h1 = h[row * 32 + c0 / 4 + 1];
        float4 o0, o1;
        o0.x = v0.x + bb0.x + h0.x;  o0.y = v0.y + bb0.y + h0.y;
        o0.z = v1.x + bb1.x + h0.z;  o0.w = v1.y + bb1.y + h0.w;
        o1.x = v2.x + bb2.x + h1.x;  o1.y = v2.y + bb2.y + h1.y;
        o1.z = v3.x + bb3.x + h1.z;  o1.w = v3.y + bb3.y + h1.w;
        out[row * 32 + c0 / 4 + 0] = o0;
        out[row * 32 + c0 / 4 + 1] = o1;
    }
}

// ---------------- launch ----------------
extern "C" void kernel_launch(void* const* d_in, const int* in_sizes, int n_in,
                              void* d_out, int out_size)
{
    const float* h   = (const float*)d_in[0];
    const int*   ei  = (const int*)  d_in[1];
    const float* ea  = (const float*)d_in[2];
    const float* bw  = (const float*)d_in[3];
    const float* bb  = (const float*)d_in[4];
    const float* bm  = (const float*)d_in[5];
    const float* bv  = (const float*)d_in[6];
    const float* tp  = (const float*)d_in[7];
    const float* W1  = (const float*)d_in[8];
    const float* b1  = (const float*)d_in[9];
    const float* lnw = (const float*)d_in[10];
    const float* lnb = (const float*)d_in[11];
    const float* W2  = (const float*)d_in[12];
    const float* b2  = (const float*)d_in[13];

    int n = in_sizes[0] / HF;
    int e = in_sizes[2] / HF;
    const int* src = ei;
    const int* dst = ei + e;

    cudaFuncSetAttribute(k_gemm1, cudaFuncAttributeMaxDynamicSharedMemorySize, SMEM1);
    cudaFuncSetAttribute(k_gemm2, cudaFuncAttributeMaxDynamicSharedMemorySize, SMEM2);

    k_hn<<<(n * HV + 255) / 256, 256>>>((const float4*)h, (const float4*)bw,
                                        (const float4*)bb, (const float4*)bm,
                                        (const float4*)bv, n);
    k_hist<<<(e + 255) / 256, 256>>>(dst, e);
    k_scan<<<1, 1024>>>(n);
    k_scatter<<<(e + 255) / 256, 256>>>(src, dst, e);
    k_agg<<<(n + 7) / 8, 256>>>((const float4*)ea, tp, n);
    k_gemm1<<<(n + 63) / 64, 256, SMEM1>>>(W1, b1, n);
    k_gemm2<<<(n + 63) / 64, 256, SMEM2>>>(W2, b2, lnw, lnb,
                                           (const float4*)h, (float4*)d_out, n);
}

// round 2
// speedup vs baseline: 1.0272x; 1.0272x over previous
#include <cuda_runtime.h>

typedef unsigned long long ull;

#define HF 128
#define HV 32           // float4 per feature row
#define NMAX 50016
#define EMAX 800032

// ---------------- scratch (static device memory; no allocation) ----------------
__device__ float g_hn[NMAX * HF];        // relu(BN(x))
__device__ float g_u [NMAX * HF];        // agg + hn  (MLP input)
__device__ float g_y1[NMAX * 2 * HF];    // GEMM1 output (pre-LN)
__device__ int   g_deg[NMAX];
__device__ int   g_rs [NMAX + 1];
__device__ int   g_cur[NMAX];
__device__ int2  g_edges[EMAX];          // (src, eid) sorted by dst

// ---------------- f32x2 helpers ----------------
__device__ __forceinline__ ull pk(float a, float b) {
    ull r; asm("mov.b64 %0, {%1, %2};" : "=l"(r) : "f"(a), "f"(b)); return r;
}
__device__ __forceinline__ float2 upk(ull v) {
    float2 r; asm("mov.b64 {%0, %1}, %2;" : "=f"(r.x), "=f"(r.y) : "l"(v)); return r;
}
__device__ __forceinline__ ull f2fma(ull a, ull b, ull c) {
    ull d; asm("fma.rn.f32x2 %0, %1, %2, %3;" : "=l"(d) : "l"(a), "l"(b), "l"(c)); return d;
}

// ---------------- K0: hn = relu(BN(h)); also zero deg ----------------
__global__ void k_hn(const float4* __restrict__ h,
                     const float4* __restrict__ bw, const float4* __restrict__ bb,
                     const float4* __restrict__ bm, const float4* __restrict__ bv,
                     int n)
{
    int i = blockIdx.x * blockDim.x + threadIdx.x;
    if (i < n) g_deg[i] = 0;
    if (i >= n * HV) return;
    int j = i & (HV - 1);
    float4 x = h[i];
    float4 w = bw[j], b = bb[j], m = bm[j], v = bv[j];
    float4 o;
    o.x = fmaxf((x.x - m.x) * rsqrtf(v.x + 1e-5f) * w.x + b.x, 0.f);
    o.y = fmaxf((x.y - m.y) * rsqrtf(v.y + 1e-5f) * w.y + b.y, 0.f);
    o.z = fmaxf((x.z - m.z) * rsqrtf(v.z + 1e-5f) * w.z + b.z, 0.f);
    o.w = fmaxf((x.w - m.w) * rsqrtf(v.w + 1e-5f) * w.w + b.w, 0.f);
    ((float4*)g_hn)[i] = o;
}

// ---------------- K1: degree histogram ----------------
__global__ void k_hist(const int* __restrict__ dst, int e)
{
    int i = blockIdx.x * blockDim.x + threadIdx.x;
    if (i < e) atomicAdd(&g_deg[dst[i]], 1);
}

// ---------------- K2: exclusive scan over deg (single block) ----------------
__global__ void k_scan(int n)
{
    __shared__ int warp_sums[32];
    int tid = threadIdx.x;
    int chunk = (n + 1023) / 1024;
    int b = tid * chunk;
    int e = min(b + chunk, n);
    int s = 0;
    for (int i = b; i < e; ++i) s += g_deg[i];
    int lane = tid & 31, wid = tid >> 5;
    int v = s;
    #pragma unroll
    for (int o = 1; o < 32; o <<= 1) {
        int u = __shfl_up_sync(0xffffffffu, v, o);
        if (lane >= o) v += u;
    }
    if (lane == 31) warp_sums[wid] = v;
    __syncthreads();
    if (wid == 0) {
        int w = warp_sums[lane];
        #pragma unroll
        for (int o = 1; o < 32; o <<= 1) {
            int u = __shfl_up_sync(0xffffffffu, w, o);
            if (lane >= o) w += u;
        }
        warp_sums[lane] = w;
    }
    __syncthreads();
    int incl = v + (wid > 0 ? warp_sums[wid - 1] : 0);
    int run = incl - s;           // exclusive
    for (int i = b; i < e; ++i) {
        g_rs[i] = run; g_cur[i] = run;
        run += g_deg[i];
    }
    if (tid == 0) g_rs[n] = warp_sums[31];
}

// ---------------- K3: scatter edges by dst (single ST.64 per edge) ----------------
__global__ void k_scatter(const int* __restrict__ src, const int* __restrict__ dst, int e)
{
    int i = blockIdx.x * blockDim.x + threadIdx.x;
    if (i >= e) return;
    int d = dst[i];
    int s = src[i];
    int p = atomicAdd(&g_cur[d], 1);
    g_edges[p] = make_int2(s, i);
}

// ---------------- K4: one-pass softmax aggregation (warp per dst node) ----------------
#define EDGE_ACC(a, hv)                                               \
    {                                                                 \
        float m0 = fmaxf(a.x + hv.x, 0.f) + 1e-7f;                    \
        float m1 = fmaxf(a.y + hv.y, 0.f) + 1e-7f;                    \
        float m2 = fmaxf(a.z + hv.z, 0.f) + 1e-7f;                    \
        float m3 = fmaxf(a.w + hv.w, 0.f) + 1e-7f;                    \
        float e0 = __expf(m0 * t);                                    \
        float e1 = __expf(m1 * t);                                    \
        float e2 = __expf(m2 * t);                                    \
        float e3 = __expf(m3 * t);                                    \
        S.x += e0; P.x = fmaf(m0, e0, P.x);                           \
        S.y += e1; P.y = fmaf(m1, e1, P.y);                           \
        S.z += e2; P.z = fmaf(m2, e2, P.z);                           \
        S.w += e3; P.w = fmaf(m3, e3, P.w);                           \
    }

__global__ void __launch_bounds__(256) k_agg(const float4* __restrict__ ea,
                                             const float* __restrict__ tp, int n)
{
    int warp = (blockIdx.x * blockDim.x + threadIdx.x) >> 5;
    int lane = threadIdx.x & 31;
    if (warp >= n) return;
    float t = __ldg(tp);
    int s0 = g_rs[warp], s1 = g_rs[warp + 1];
    const float4* hn4 = (const float4*)g_hn;
    float4 S = make_float4(0.f, 0.f, 0.f, 0.f);
    float4 P = make_float4(0.f, 0.f, 0.f, 0.f);

    int i = s0;
    for (; i + 4 <= s1; i += 4) {
        int2 q0 = g_edges[i + 0];
        int2 q1 = g_edges[i + 1];
        int2 q2 = g_edges[i + 2];
        int2 q3 = g_edges[i + 3];
        // issue all 8 wide loads before any math (MLP = 8)
        float4 a0 = ea [(size_t)q0.y * HV + lane];
        float4 h0 = hn4[(size_t)q0.x * HV + lane];
        float4 a1 = ea [(size_t)q1.y * HV + lane];
        float4 h1 = hn4[(size_t)q1.x * HV + lane];
        float4 a2 = ea [(size_t)q2.y * HV + lane];
        float4 h2 = hn4[(size_t)q2.x * HV + lane];
        float4 a3 = ea [(size_t)q3.y * HV + lane];
        float4 h3 = hn4[(size_t)q3.x * HV + lane];
        EDGE_ACC(a0, h0);
        EDGE_ACC(a1, h1);
        EDGE_ACC(a2, h2);
        EDGE_ACC(a3, h3);
    }
    for (; i < s1; ++i) {
        int2 q = g_edges[i];
        float4 a  = ea [(size_t)q.y * HV + lane];
        float4 hv = hn4[(size_t)q.x * HV + lane];
        EDGE_ACC(a, hv);
    }

    float4 hd = hn4[warp * HV + lane];
    float4 u;
    u.x = P.x / (S.x + 1e-16f) + hd.x;
    u.y = P.y / (S.y + 1e-16f) + hd.y;
    u.z = P.z / (S.z + 1e-16f) + hd.z;
    u.w = P.w / (S.w + 1e-16f) + hd.w;
    ((float4*)g_u)[warp * HV + lane] = u;
}

// ---------------- K5: GEMM1  y1 = u @ W1 + b1   (64 rows/block, FFMA2) ----------------
#define SMEM1 ((128 * 256 + 128 * 64) * 4)
__global__ void __launch_bounds__(256) k_gemm1(const float* __restrict__ W1,
                                               const float* __restrict__ b1, int n)
{
    extern __shared__ float sm[];
    float* Ws = sm;               // [128][256]
    float* Ut = sm + 128 * 256;   // [128][64] k-major
    int tid = threadIdx.x;
    int row0 = blockIdx.x * 64;

    for (int i = tid; i < (128 * 256) / 4; i += 256)
        ((float4*)Ws)[i] = ((const float4*)W1)[i];

    const float4* U4 = (const float4*)g_u;
    for (int i = tid; i < 64 * 32; i += 256) {
        int r = i >> 5, j = i & 31;
        float4 v = (row0 + r < n) ? U4[(row0 + r) * 32 + j] : make_float4(0.f, 0.f, 0.f, 0.f);
        int k = 4 * j;
        Ut[(k + 0) * 64 + r] = v.x;
        Ut[(k + 1) * 64 + r] = v.y;
        Ut[(k + 2) * 64 + r] = v.z;
        Ut[(k + 3) * 64 + r] = v.w;
    }
    __syncthreads();

    int rg = tid & 15, cg = tid >> 4;
    int r0 = rg * 4, c0 = cg * 16;
    ull acc[4][8];
    #pragma unroll
    for (int a = 0; a < 4; ++a)
        #pragma unroll
        for (int p = 0; p < 8; ++p) acc[a][p] = 0ull;

    for (int k = 0; k < 128; ++k) {
        float4 xv = *(const float4*)(Ut + k * 64 + r0);
        ull x0 = pk(xv.x, xv.x), x1 = pk(xv.y, xv.y);
        ull x2 = pk(xv.z, xv.z), x3 = pk(xv.w, xv.w);
        const ull* wr = (const ull*)(Ws + k * 256 + c0);
        #pragma unroll
        for (int p = 0; p < 8; ++p) {
            ull wv = wr[p];
            acc[0][p] = f2fma(x0, wv, acc[0][p]);
            acc[1][p] = f2fma(x1, wv, acc[1][p]);
            acc[2][p] = f2fma(x2, wv, acc[2][p]);
            acc[3][p] = f2fma(x3, wv, acc[3][p]);
        }
    }

    const float2* b12 = (const float2*)b1;
    #pragma unroll
    for (int rr = 0; rr < 4; ++rr) {
        int row = row0 + r0 + rr;
        if (row >= n) break;
        float2* out = (float2*)(g_y1 + (size_t)row * 256 + c0);
        #pragma unroll
        for (int p = 0; p < 8; ++p) {
            float2 v = upk(acc[rr][p]);
            float2 bb = b12[c0 / 2 + p];
            v.x += bb.x; v.y += bb.y;
            out[p] = v;
        }
    }
}

// ---------------- K6: LN + relu + GEMM2 + bias + residual ----------------
#define SMEM2 ((256 * 128 + 256 * 64) * 4)
__global__ void __launch_bounds__(256) k_gemm2(const float* __restrict__ W2,
                                               const float* __restrict__ b2,
                                               const float* __restrict__ lnw,
                                               const float* __restrict__ lnb,
                                               const float4* __restrict__ h,
                                               float4* __restrict__ out, int n)
{
    extern __shared__ float sm[];
    float* Ws = sm;               // [256][128]
    float* Yt = sm + 256 * 128;   // [256][64] k-major
    __shared__ float s_lnw[256], s_lnb[256];
    __shared__ float s_red[256], s_red2[256];
    __shared__ float s_mean[64], s_scale[64];
    int tid = threadIdx.x;
    int row0 = blockIdx.x * 64;

    for (int i = tid; i < (256 * 128) / 4; i += 256)
        ((float4*)Ws)[i] = ((const float4*)W2)[i];
    s_lnw[tid] = lnw[tid];
    s_lnb[tid] = lnb[tid];

    const float4* Y4 = (const float4*)g_y1;
    for (int i = tid; i < 64 * 64; i += 256) {
        int r = i >> 6, j = i & 63;
        float4 v = (row0 + r < n) ? Y4[(size_t)(row0 + r) * 64 + j] : make_float4(0.f, 0.f, 0.f, 0.f);
        int k = 4 * j;
        Yt[(k + 0) * 64 + r] = v.x;
        Yt[(k + 1) * 64 + r] = v.y;
        Yt[(k + 2) * 64 + r] = v.z;
        Yt[(k + 3) * 64 + r] = v.w;
    }
    __syncthreads();

    {   // LayerNorm stats (4 partial reducers per row)
        int r = tid & 63, part = tid >> 6;
        float s = 0.f, s2 = 0.f;
        for (int k = part * 64; k < part * 64 + 64; ++k) {
            float v = Yt[k * 64 + r];
            s += v; s2 = fmaf(v, v, s2);
        }
        s_red[tid] = s; s_red2[tid] = s2;
    }
    __syncthreads();
    if (tid < 64) {
        float s  = s_red[tid]  + s_red[64 + tid]  + s_red[128 + tid]  + s_red[192 + tid];
        float s2 = s_red2[tid] + s_red2[64 + tid] + s_red2[128 + tid] + s_red2[192 + tid];
        float mean = s * (1.f / 256.f);
        float var = fmaxf(s2 * (1.f / 256.f) - mean * mean, 0.f);
        s_mean[tid] = mean;
        s_scale[tid] = rsqrtf(var + 1e-5f);
    }
    __syncthreads();
    for (int i = tid; i < 256 * 64; i += 256) {
        int k = i >> 6, r = i & 63;
        float v = (Yt[i] - s_mean[r]) * s_scale[r] * s_lnw[k] + s_lnb[k];
        Yt[i] = fmaxf(v, 0.f);
    }
    __syncthreads();

    int rg = tid & 15, cg = tid >> 4;
    int r0 = rg * 4, c0 = cg * 8;
    ull acc[4][4];
    #pragma unroll
    for (int a = 0; a < 4; ++a)
        #pragma unroll
        for (int p = 0; p < 4; ++p) acc[a][p] = 0ull;

    for (int k = 0; k < 256; ++k) {
        float4 xv = *(const float4*)(Yt + k * 64 + r0);
        ull x0 = pk(xv.x, xv.x), x1 = pk(xv.y, xv.y);
        ull x2 = pk(xv.z, xv.z), x3 = pk(xv.w, xv.w);
        const ull* wr = (const ull*)(Ws + k * 128 + c0);
        #pragma unroll
        for (int p = 0; p < 4; ++p) {
            ull wv = wr[p];
            acc[0][p] = f2fma(x0, wv, acc[0][p]);
            acc[1][p] = f2fma(x1, wv, acc[1][p]);
            acc[2][p] = f2fma(x2, wv, acc[2][p]);
            acc[3][p] = f2fma(x3, wv, acc[3][p]);
        }
    }

    const float2* b22 = (const float2*)b2;
    #pragma unroll
    for (int rr = 0; rr < 4; ++rr) {
        int row = row0 + r0 + rr;
        if (row >= n) break;
        float2 v0 = upk(acc[rr][0]), v1 = upk(acc[rr][1]);
        float2 v2 = upk(acc[rr][2]), v3 = upk(acc[rr][3]);
        float2 bb0 = b22[c0 / 2 + 0], bb1 = b22[c0 / 2 + 1];
        float2 bb2 = b22[c0 / 2 + 2], bb3 = b22[c0 / 2 + 3];
        float4 h0 = h[row * 32 + c0 / 4 + 0];
        float4 h1 = h[row * 32 + c0 / 4 + 1];
        float4 o0, o1;
        o0.x = v0.x + bb0.x + h0.x;  o0.y = v0.y + bb0.y + h0.y;
        o0.z = v1.x + bb1.x + h0.z;  o0.w = v1.y + bb1.y + h0.w;
        o1.x = v2.x + bb2.x + h1.x;  o1.y = v2.y + bb2.y + h1.y;
        o1.z = v3.x + bb3.x + h1.z;  o1.w = v3.y + bb3.y + h1.w;
        out[row * 32 + c0 / 4 + 0] = o0;
        out[row * 32 + c0 / 4 + 1] = o1;
    }
}

// ---------------- launch ----------------
extern "C" void kernel_launch(void* const* d_in, const int* in_sizes, int n_in,
                              void* d_out, int out_size)
{
    const float* h   = (const float*)d_in[0];
    const int*   ei  = (const int*)  d_in[1];
    const float* ea  = (const float*)d_in[2];
    const float* bw  = (const float*)d_in[3];
    const float* bb  = (const float*)d_in[4];
    const float* bm  = (const float*)d_in[5];
    const float* bv  = (const float*)d_in[6];
    const float* tp  = (const float*)d_in[7];
    const float* W1  = (const float*)d_in[8];
    const float* b1  = (const float*)d_in[9];
    const float* lnw = (const float*)d_in[10];
    const float* lnb = (const float*)d_in[11];
    const float* W2  = (const float*)d_in[12];
    const float* b2  = (const float*)d_in[13];

    int n = in_sizes[0] / HF;
    int e = in_sizes[2] / HF;
    const int* src = ei;
    const int* dst = ei + e;

    cudaFuncSetAttribute(k_gemm1, cudaFuncAttributeMaxDynamicSharedMemorySize, SMEM1);
    cudaFuncSetAttribute(k_gemm2, cudaFuncAttributeMaxDynamicSharedMemorySize, SMEM2);

    k_hn<<<(n * HV + 255) / 256, 256>>>((const float4*)h, (const float4*)bw,
                                        (const float4*)bb, (const float4*)bm,
                                        (const float4*)bv, n);
    k_hist<<<(e + 255) / 256, 256>>>(dst, e);
    k_scan<<<1, 1024>>>(n);
    k_scatter<<<(e + 255) / 256, 256>>>(src, dst, e);
    k_agg<<<(n + 7) / 8, 256>>>((const float4*)ea, tp, n);
    k_gemm1<<<(n + 63) / 64, 256, SMEM1>>>(W1, b1, n);
    k_gemm2<<<(n + 63) / 64, 256, SMEM2>>>(W2, b2, lnw, lnb,
                                           (const float4*)h, (float4*)d_out, n);
}

// round 3
// speedup vs baseline: 1.2195x; 1.1872x over previous
#include <cuda_runtime.h>

typedef unsigned long long ull;

#define HF 128
#define HV 32           // float4 per feature row
#define NMAX 50016
#define EMAX 800032

// ---------------- scratch (static device memory; no allocation) ----------------
__device__ float g_hn[NMAX * HF];        // relu(BN(x))
__device__ float g_u [NMAX * HF];        // agg + hn  (MLP input)
__device__ int   g_cnt[NMAX];            // degree histogram (zeroed by k_scan for next replay)
__device__ int   g_rs [NMAX + 1];
__device__ int   g_cur[NMAX];
__device__ int2  g_edges[EMAX];          // (src, eid) sorted by dst

// ---------------- f32x2 helpers ----------------
__device__ __forceinline__ ull pk(float a, float b) {
    ull r; asm("mov.b64 %0, {%1, %2};" : "=l"(r) : "f"(a), "f"(b)); return r;
}
__device__ __forceinline__ float2 upk(ull v) {
    float2 r; asm("mov.b64 {%0, %1}, %2;" : "=f"(r.x), "=f"(r.y) : "l"(v)); return r;
}
__device__ __forceinline__ ull f2fma(ull a, ull b, ull c) {
    ull d; asm("fma.rn.f32x2 %0, %1, %2, %3;" : "=l"(d) : "l"(a), "l"(b), "l"(c)); return d;
}

// ---------------- K0: hn = relu(BN(h))  +  degree histogram ----------------
__global__ void k_hn_hist(const float4* __restrict__ h,
                          const float4* __restrict__ bw, const float4* __restrict__ bb,
                          const float4* __restrict__ bm, const float4* __restrict__ bv,
                          const int* __restrict__ dst, int n, int e)
{
    int i = blockIdx.x * blockDim.x + threadIdx.x;
    if (i < e) atomicAdd(&g_cnt[dst[i]], 1);
    if (i >= n * HV) return;
    int j = i & (HV - 1);
    float4 x = h[i];
    float4 w = bw[j], b = bb[j], m = bm[j], v = bv[j];
    float4 o;
    o.x = fmaxf((x.x - m.x) * rsqrtf(v.x + 1e-5f) * w.x + b.x, 0.f);
    o.y = fmaxf((x.y - m.y) * rsqrtf(v.y + 1e-5f) * w.y + b.y, 0.f);
    o.z = fmaxf((x.z - m.z) * rsqrtf(v.z + 1e-5f) * w.z + b.z, 0.f);
    o.w = fmaxf((x.w - m.w) * rsqrtf(v.w + 1e-5f) * w.w + b.w, 0.f);
    ((float4*)g_hn)[i] = o;
}

// ---------------- K1: exclusive scan over counts (single block); re-zero counts ----------------
__global__ void k_scan(int n)
{
    __shared__ int warp_sums[32];
    int tid = threadIdx.x;
    int chunk = (n + 1023) / 1024;
    int b = tid * chunk;
    int e = min(b + chunk, n);
    int s = 0;
    for (int i = b; i < e; ++i) s += g_cnt[i];
    int lane = tid & 31, wid = tid >> 5;
    int v = s;
    #pragma unroll
    for (int o = 1; o < 32; o <<= 1) {
        int u = __shfl_up_sync(0xffffffffu, v, o);
        if (lane >= o) v += u;
    }
    if (lane == 31) warp_sums[wid] = v;
    __syncthreads();
    if (wid == 0) {
        int w = warp_sums[lane];
        #pragma unroll
        for (int o = 1; o < 32; o <<= 1) {
            int u = __shfl_up_sync(0xffffffffu, w, o);
            if (lane >= o) w += u;
        }
        warp_sums[lane] = w;
    }
    __syncthreads();
    int incl = v + (wid > 0 ? warp_sums[wid - 1] : 0);
    int run = incl - s;           // exclusive
    for (int i = b; i < e; ++i) {
        int d = g_cnt[i];
        g_rs[i] = run; g_cur[i] = run;
        g_cnt[i] = 0;             // ready for next replay
        run += d;
    }
    if (tid == 0) g_rs[n] = warp_sums[31];
}

// ---------------- K2: scatter edges by dst (single ST.64 per edge) ----------------
__global__ void k_scatter(const int* __restrict__ src, const int* __restrict__ dst, int e)
{
    int i = blockIdx.x * blockDim.x + threadIdx.x;
    if (i >= e) return;
    int d = dst[i];
    int s = src[i];
    int p = atomicAdd(&g_cur[d], 1);
    g_edges[p] = make_int2(s, i);
}

// ---------------- K3: one-pass softmax aggregation (warp per dst node) ----------------
#define EDGE_ACC(a, hv)                                               \
    {                                                                 \
        float m0 = fmaxf(a.x + hv.x, 0.f) + 1e-7f;                    \
        float m1 = fmaxf(a.y + hv.y, 0.f) + 1e-7f;                    \
        float m2 = fmaxf(a.z + hv.z, 0.f) + 1e-7f;                    \
        float m3 = fmaxf(a.w + hv.w, 0.f) + 1e-7f;                    \
        float e0 = __expf(m0 * t);                                    \
        float e1 = __expf(m1 * t);                                    \
        float e2 = __expf(m2 * t);                                    \
        float e3 = __expf(m3 * t);                                    \
        S.x += e0; P.x = fmaf(m0, e0, P.x);                           \
        S.y += e1; P.y = fmaf(m1, e1, P.y);                           \
        S.z += e2; P.z = fmaf(m2, e2, P.z);                           \
        S.w += e3; P.w = fmaf(m3, e3, P.w);                           \
    }

__global__ void __launch_bounds__(256) k_agg(const float4* __restrict__ ea,
                                             const float* __restrict__ tp, int n)
{
    int warp = (blockIdx.x * blockDim.x + threadIdx.x) >> 5;
    int lane = threadIdx.x & 31;
    if (warp >= n) return;
    float t = __ldg(tp);
    int s0 = g_rs[warp], s1 = g_rs[warp + 1];
    const float4* hn4 = (const float4*)g_hn;
    float4 S = make_float4(0.f, 0.f, 0.f, 0.f);
    float4 P = make_float4(0.f, 0.f, 0.f, 0.f);

    int i = s0;
    for (; i + 4 <= s1; i += 4) {
        int2 q0 = g_edges[i + 0];
        int2 q1 = g_edges[i + 1];
        int2 q2 = g_edges[i + 2];
        int2 q3 = g_edges[i + 3];
        float4 a0 = ea [(size_t)q0.y * HV + lane];
        float4 h0 = hn4[(size_t)q0.x * HV + lane];
        float4 a1 = ea [(size_t)q1.y * HV + lane];
        float4 h1 = hn4[(size_t)q1.x * HV + lane];
        float4 a2 = ea [(size_t)q2.y * HV + lane];
        float4 h2 = hn4[(size_t)q2.x * HV + lane];
        float4 a3 = ea [(size_t)q3.y * HV + lane];
        float4 h3 = hn4[(size_t)q3.x * HV + lane];
        EDGE_ACC(a0, h0);
        EDGE_ACC(a1, h1);
        EDGE_ACC(a2, h2);
        EDGE_ACC(a3, h3);
    }
    for (; i < s1; ++i) {
        int2 q = g_edges[i];
        float4 a  = ea [(size_t)q.y * HV + lane];
        float4 hv = hn4[(size_t)q.x * HV + lane];
        EDGE_ACC(a, hv);
    }

    float4 hd = hn4[warp * HV + lane];
    float4 u;
    u.x = P.x / (S.x + 1e-16f) + hd.x;
    u.y = P.y / (S.y + 1e-16f) + hd.y;
    u.z = P.z / (S.z + 1e-16f) + hd.z;
    u.w = P.w / (S.w + 1e-16f) + hd.w;
    ((float4*)g_u)[warp * HV + lane] = u;
}

// ---------------- K4: fused MLP  (GEMM1 + bias + LN + relu + GEMM2 + bias + residual) ----------------
// 32 rows per block. smem: Ws 64KB (K-half of W1 / W2) + Ut 16KB + Yt 32KB = 112KB -> 2 blocks/SM.
#define SMEMM ((16384 + 4096 + 8192) * 4)
__global__ void __launch_bounds__(256) k_mlp(const float* __restrict__ W1,
                                             const float* __restrict__ b1,
                                             const float* __restrict__ lnw,
                                             const float* __restrict__ lnb,
                                             const float* __restrict__ W2,
                                             const float* __restrict__ b2,
                                             const float4* __restrict__ h,
                                             float4* __restrict__ out, int n)
{
    extern __shared__ float sm[];
    float* Ws = sm;                 // 16384 floats: staged weight half
    float* Ut = sm + 16384;         // 4096 floats: u^T [128][32]; later LN scratch
    float* Yt = sm + 16384 + 4096;  // 8192 floats: y1^T [256][32]
    int tid = threadIdx.x;
    int row0 = blockIdx.x * 32;

    // ---- load u^T (conflict-free STS: lanes write distinct rows r) ----
    {
        const float4* U4 = (const float4*)g_u;
        for (int i = tid; i < 32 * 32; i += 256) {
            int r = i & 31, j = i >> 5;
            float4 v = (row0 + r < n) ? U4[(size_t)(row0 + r) * 32 + j]
                                      : make_float4(0.f, 0.f, 0.f, 0.f);
            int k = 4 * j;
            Ut[(k + 0) * 32 + r] = v.x;
            Ut[(k + 1) * 32 + r] = v.y;
            Ut[(k + 2) * 32 + r] = v.z;
            Ut[(k + 3) * 32 + r] = v.w;
        }
    }

    int rg = tid & 7, cg = tid >> 3;
    int r0 = rg * 4;

    // ================= GEMM1: y1[32][256] = u @ W1 =================
    ull acc[4][4];
    #pragma unroll
    for (int a = 0; a < 4; ++a)
        #pragma unroll
        for (int p = 0; p < 4; ++p) acc[a][p] = 0ull;

    int c1 = cg * 8;   // output col group (8 cols)
    #pragma unroll
    for (int kk = 0; kk < 2; ++kk) {
        __syncthreads();
        const float4* wsrc = (const float4*)(W1 + kk * 64 * 256);
        for (int i = tid; i < 4096; i += 256) ((float4*)Ws)[i] = wsrc[i];
        __syncthreads();
        for (int k = 0; k < 64; ++k) {
            float4 xv = *(const float4*)(Ut + (kk * 64 + k) * 32 + r0);
            ull x0 = pk(xv.x, xv.x), x1 = pk(xv.y, xv.y);
            ull x2 = pk(xv.z, xv.z), x3 = pk(xv.w, xv.w);
            const ull* wr = (const ull*)(Ws + k * 256 + c1);
            #pragma unroll
            for (int p = 0; p < 4; ++p) {
                ull wv = wr[p];
                acc[0][p] = f2fma(x0, wv, acc[0][p]);
                acc[1][p] = f2fma(x1, wv, acc[1][p]);
                acc[2][p] = f2fma(x2, wv, acc[2][p]);
                acc[3][p] = f2fma(x3, wv, acc[3][p]);
            }
        }
    }

    // epilogue: Yt[c][r] = y1 + b1   (transposed store)
    #pragma unroll
    for (int p = 0; p < 4; ++p) {
        float2 bb = ((const float2*)b1)[c1 / 2 + p];
        #pragma unroll
        for (int rr = 0; rr < 4; ++rr) {
            float2 v = upk(acc[rr][p]);
            Yt[(c1 + 2 * p + 0) * 32 + r0 + rr] = v.x + bb.x;
            Yt[(c1 + 2 * p + 1) * 32 + r0 + rr] = v.y + bb.y;
        }
    }

    // ---- stage W2 half0 while Yt settles; also stage LN params into dead Ut ----
    float* s_red   = Ut;         // 256
    float* s_red2  = Ut + 256;   // 256
    float* s_mean  = Ut + 512;   // 32
    float* s_scale = Ut + 544;   // 32
    float* s_lnw   = Ut + 576;   // 256
    float* s_lnb   = Ut + 832;   // 256
    __syncthreads();             // Ut/Ws reads done; Yt writes done
    {
        const float4* wsrc = (const float4*)W2;   // rows 0..127
        for (int i = tid; i < 4096; i += 256) ((float4*)Ws)[i] = wsrc[i];
        s_lnw[tid] = lnw[tid];
        s_lnb[tid] = lnb[tid];
    }

    // ---- LayerNorm stats: 8 partials x 32 rows ----
    {
        int r = tid & 31, part = tid >> 5;
        float s = 0.f, s2 = 0.f;
        for (int k = part * 32; k < part * 32 + 32; ++k) {
            float v = Yt[k * 32 + r];
            s += v; s2 = fmaf(v, v, s2);
        }
        s_red[tid] = s; s_red2[tid] = s2;
    }
    __syncthreads();
    if (tid < 32) {
        float s = 0.f, s2 = 0.f;
        #pragma unroll
        for (int p = 0; p < 8; ++p) { s += s_red[p * 32 + tid]; s2 += s_red2[p * 32 + tid]; }
        float mean = s * (1.f / 256.f);
        float var = fmaxf(s2 * (1.f / 256.f) - mean * mean, 0.f);
        s_mean[tid] = mean;
        s_scale[tid] = rsqrtf(var + 1e-5f);
    }
    __syncthreads();
    for (int i = tid; i < 256 * 32; i += 256) {
        int k = i >> 5, r = i & 31;
        float v = (Yt[i] - s_mean[r]) * s_scale[r] * s_lnw[k] + s_lnb[k];
        Yt[i] = fmaxf(v, 0.f);
    }
    __syncthreads();

    // ================= GEMM2: out[32][128] = relu(LN(y1)) @ W2 =================
    ull acc2[4][2];
    #pragma unroll
    for (int a = 0; a < 4; ++a) { acc2[a][0] = 0ull; acc2[a][1] = 0ull; }

    int c2 = cg * 4;   // output col group (4 cols)
    #pragma unroll
    for (int kk = 0; kk < 2; ++kk) {
        if (kk == 1) {
            __syncthreads();
            const float4* wsrc = (const float4*)(W2 + 128 * 128);
            for (int i = tid; i < 4096; i += 256) ((float4*)Ws)[i] = wsrc[i];
            __syncthreads();
        }
        for (int k = 0; k < 128; ++k) {
            float4 xv = *(const float4*)(Yt + (kk * 128 + k) * 32 + r0);
            ull x0 = pk(xv.x, xv.x), x1 = pk(xv.y, xv.y);
            ull x2 = pk(xv.z, xv.z), x3 = pk(xv.w, xv.w);
            const ull* wr = (const ull*)(Ws + k * 128 + c2);
            ull w0 = wr[0], w1 = wr[1];
            acc2[0][0] = f2fma(x0, w0, acc2[0][0]);
            acc2[0][1] = f2fma(x0, w1, acc2[0][1]);
            acc2[1][0] = f2fma(x1, w0, acc2[1][0]);
            acc2[1][1] = f2fma(x1, w1, acc2[1][1]);
            acc2[2][0] = f2fma(x2, w0, acc2[2][0]);
            acc2[2][1] = f2fma(x2, w1, acc2[2][1]);
            acc2[3][0] = f2fma(x3, w0, acc2[3][0]);
            acc2[3][1] = f2fma(x3, w1, acc2[3][1]);
        }
    }

    // epilogue: out = y2 + b2 + h (residual)
    {
        float2 bb0 = ((const float2*)b2)[c2 / 2 + 0];
        float2 bb1 = ((const float2*)b2)[c2 / 2 + 1];
        #pragma unroll
        for (int rr = 0; rr < 4; ++rr) {
            int row = row0 + r0 + rr;
            if (row >= n) break;
            float2 v0 = upk(acc2[rr][0]);
            float2 v1 = upk(acc2[rr][1]);
            float4 hv = h[(size_t)row * 32 + c2 / 4];
            float4 o;
            o.x = v0.x + bb0.x + hv.x;
            o.y = v0.y + bb0.y + hv.y;
            o.z = v1.x + bb1.x + hv.z;
            o.w = v1.y + bb1.y + hv.w;
            out[(size_t)row * 32 + c2 / 4] = o;
        }
    }
}

// ---------------- launch ----------------
extern "C" void kernel_launch(void* const* d_in, const int* in_sizes, int n_in,
                              void* d_out, int out_size)
{
    const float* h   = (const float*)d_in[0];
    const int*   ei  = (const int*)  d_in[1];
    const float* ea  = (const float*)d_in[2];
    const float* bw  = (const float*)d_in[3];
    const float* bb  = (const float*)d_in[4];
    const float* bm  = (const float*)d_in[5];
    const float* bv  = (const float*)d_in[6];
    const float* tp  = (const float*)d_in[7];
    const float* W1  = (const float*)d_in[8];
    const float* b1  = (const float*)d_in[9];
    const float* lnw = (const float*)d_in[10];
    const float* lnb = (const float*)d_in[11];
    const float* W2  = (const float*)d_in[12];
    const float* b2  = (const float*)d_in[13];

    int n = in_sizes[0] / HF;
    int e = in_sizes[2] / HF;
    const int* src = ei;
    const int* dst = ei + e;

    cudaFuncSetAttribute(k_mlp, cudaFuncAttributeMaxDynamicSharedMemorySize, SMEMM);

    k_hn_hist<<<(n * HV + 255) / 256, 256>>>((const float4*)h, (const float4*)bw,
                                             (const float4*)bb, (const float4*)bm,
                                             (const float4*)bv, dst, n, e);
    k_scan<<<1, 1024>>>(n);
    k_scatter<<<(e + 255) / 256, 256>>>(src, dst, e);
    k_agg<<<(n + 7) / 8, 256>>>((const float4*)ea, tp, n);      // <- ncu capture lands here
    k_mlp<<<(n + 31) / 32, 256, SMEMM>>>(W1, b1, lnw, lnb, W2, b2,
                                         (const float4*)h, (float4*)d_out, n);
}

// round 4
// speedup vs baseline: 1.2371x; 1.0144x over previous
#include <cuda_runtime.h>

typedef unsigned long long ull;

#define HF 128
#define HV 32           // float4 per feature row
#define NMAX 50016
#define EMAX 800032

// ---------------- scratch (static device memory; no allocation) ----------------
__device__ float g_hn[NMAX * HF];        // relu(BN(x))
__device__ float g_u [NMAX * HF];        // agg + hn  (MLP input)
__device__ float g_y1[NMAX * 2 * HF];    // GEMM1 output (pre-LN), lives in L2
__device__ int   g_cnt[NMAX];            // degree histogram (zeroed by k_scan for next replay)
__device__ int   g_rs [NMAX + 1];
__device__ int   g_cur[NMAX];
__device__ int2  g_edges[EMAX];          // (src, eid) sorted by dst

// ---------------- f32x2 helpers ----------------
__device__ __forceinline__ ull pk(float a, float b) {
    ull r; asm("mov.b64 %0, {%1, %2};" : "=l"(r) : "f"(a), "f"(b)); return r;
}
__device__ __forceinline__ float2 upk(ull v) {
    float2 r; asm("mov.b64 {%0, %1}, %2;" : "=f"(r.x), "=f"(r.y) : "l"(v)); return r;
}
__device__ __forceinline__ ull f2fma(ull a, ull b, ull c) {
    ull d; asm("fma.rn.f32x2 %0, %1, %2, %3;" : "=l"(d) : "l"(a), "l"(b), "l"(c)); return d;
}

// ---------------- K0: hn = relu(BN(h))  +  degree histogram ----------------
__global__ void k_hn_hist(const float4* __restrict__ h,
                          const float4* __restrict__ bw, const float4* __restrict__ bb,
                          const float4* __restrict__ bm, const float4* __restrict__ bv,
                          const int* __restrict__ dst, int n, int e)
{
    int i = blockIdx.x * blockDim.x + threadIdx.x;
    if (i < e) atomicAdd(&g_cnt[dst[i]], 1);
    if (i >= n * HV) return;
    int j = i & (HV - 1);
    float4 x = h[i];
    float4 w = bw[j], b = bb[j], m = bm[j], v = bv[j];
    float4 o;
    o.x = fmaxf((x.x - m.x) * rsqrtf(v.x + 1e-5f) * w.x + b.x, 0.f);
    o.y = fmaxf((x.y - m.y) * rsqrtf(v.y + 1e-5f) * w.y + b.y, 0.f);
    o.z = fmaxf((x.z - m.z) * rsqrtf(v.z + 1e-5f) * w.z + b.z, 0.f);
    o.w = fmaxf((x.w - m.w) * rsqrtf(v.w + 1e-5f) * w.w + b.w, 0.f);
    ((float4*)g_hn)[i] = o;
}

// ---------------- K1: coalesced exclusive scan (single block, 1024 thr) ----------------
__global__ void k_scan(int n)
{
    __shared__ int wsum[32];
    __shared__ int s_carry;
    int tid = threadIdx.x, lane = tid & 31, wid = tid >> 5;
    if (tid == 0) s_carry = 0;
    __syncthreads();
    int nIter = (n + 1023) >> 10;
    for (int it = 0; it < nIter; ++it) {
        int idx = (it << 10) + tid;
        int v = (idx < n) ? g_cnt[idx] : 0;
        int x = v;
        #pragma unroll
        for (int o = 1; o < 32; o <<= 1) {
            int u = __shfl_up_sync(0xffffffffu, x, o);
            if (lane >= o) x += u;
        }
        if (lane == 31) wsum[wid] = x;
        __syncthreads();
        if (wid == 0) {
            int w = wsum[lane];
            #pragma unroll
            for (int o = 1; o < 32; o <<= 1) {
                int u = __shfl_up_sync(0xffffffffu, w, o);
                if (lane >= o) w += u;
            }
            wsum[lane] = w;
        }
        __syncthreads();
        int carry = s_carry;
        int excl = x - v + (wid > 0 ? wsum[wid - 1] : 0) + carry;
        if (idx < n) { g_rs[idx] = excl; g_cur[idx] = excl; g_cnt[idx] = 0; }
        __syncthreads();
        if (tid == 0) s_carry = carry + wsum[31];
        __syncthreads();
    }
    if (tid == 0) g_rs[n] = s_carry;
}

// ---------------- K2: scatter edges by dst (single ST.64 per edge) ----------------
__global__ void k_scatter(const int* __restrict__ src, const int* __restrict__ dst, int e)
{
    int i = blockIdx.x * blockDim.x + threadIdx.x;
    if (i >= e) return;
    int d = dst[i];
    int s = src[i];
    int p = atomicAdd(&g_cur[d], 1);
    g_edges[p] = make_int2(s, i);
}

// ---------------- K3: one-pass softmax aggregation (warp per dst node) ----------------
#define EDGE_ACC(a, hv)                                               \
    {                                                                 \
        float m0 = fmaxf(a.x + hv.x, 0.f) + 1e-7f;                    \
        float m1 = fmaxf(a.y + hv.y, 0.f) + 1e-7f;                    \
        float m2 = fmaxf(a.z + hv.z, 0.f) + 1e-7f;                    \
        float m3 = fmaxf(a.w + hv.w, 0.f) + 1e-7f;                    \
        float e0 = __expf(m0 * t);                                    \
        float e1 = __expf(m1 * t);                                    \
        float e2 = __expf(m2 * t);                                    \
        float e3 = __expf(m3 * t);                                    \
        S.x += e0; P.x = fmaf(m0, e0, P.x);                           \
        S.y += e1; P.y = fmaf(m1, e1, P.y);                           \
        S.z += e2; P.z = fmaf(m2, e2, P.z);                           \
        S.w += e3; P.w = fmaf(m3, e3, P.w);                           \
    }

__global__ void __launch_bounds__(256) k_agg(const float4* __restrict__ ea,
                                             const float* __restrict__ tp, int n)
{
    int warp = (blockIdx.x * blockDim.x + threadIdx.x) >> 5;
    int lane = threadIdx.x & 31;
    if (warp >= n) return;
    float t = __ldg(tp);
    int s0 = g_rs[warp], s1 = g_rs[warp + 1];
    const float4* hn4 = (const float4*)g_hn;
    float4 S = make_float4(0.f, 0.f, 0.f, 0.f);
    float4 P = make_float4(0.f, 0.f, 0.f, 0.f);

    int i = s0;
    for (; i + 4 <= s1; i += 4) {
        int2 q0 = g_edges[i + 0];
        int2 q1 = g_edges[i + 1];
        int2 q2 = g_edges[i + 2];
        int2 q3 = g_edges[i + 3];
        float4 a0 = ea [(size_t)q0.y * HV + lane];
        float4 h0 = hn4[(size_t)q0.x * HV + lane];
        float4 a1 = ea [(size_t)q1.y * HV + lane];
        float4 h1 = hn4[(size_t)q1.x * HV + lane];
        float4 a2 = ea [(size_t)q2.y * HV + lane];
        float4 h2 = hn4[(size_t)q2.x * HV + lane];
        float4 a3 = ea [(size_t)q3.y * HV + lane];
        float4 h3 = hn4[(size_t)q3.x * HV + lane];
        EDGE_ACC(a0, h0);
        EDGE_ACC(a1, h1);
        EDGE_ACC(a2, h2);
        EDGE_ACC(a3, h3);
    }
    for (; i < s1; ++i) {
        int2 q = g_edges[i];
        float4 a  = ea [(size_t)q.y * HV + lane];
        float4 hv = hn4[(size_t)q.x * HV + lane];
        EDGE_ACC(a, hv);
    }

    float4 hd = hn4[warp * HV + lane];
    float4 u;
    u.x = P.x / (S.x + 1e-16f) + hd.x;
    u.y = P.y / (S.y + 1e-16f) + hd.y;
    u.z = P.z / (S.z + 1e-16f) + hd.z;
    u.w = P.w / (S.w + 1e-16f) + hd.w;
    ((float4*)g_u)[warp * HV + lane] = u;
}

// ---------------- K4: persistent GEMM1  y1 = u @ W1 + b1 ----------------
// 1 block/SM, 512 threads, W1 (128KB) resident in smem; block-strided 64-row tiles.
#define SMEMG1 ((32768 + 8192) * 4)
__global__ void __launch_bounds__(512) k_gemm1p(const float4* __restrict__ W1,
                                                const float* __restrict__ b1,
                                                int n, int ntiles)
{
    extern __shared__ float sm[];
    float* Ws = sm;            // [128][256]  full W1
    float* Ut = sm + 32768;    // [128][64]   u^T tile
    int tid = threadIdx.x;

    for (int i = tid; i < 8192; i += 512)
        ((float4*)Ws)[i] = W1[i];

    int rg = tid & 15, cg = tid >> 4;        // rg in [0,16), cg in [0,32)
    int r0 = rg * 4, c1 = cg * 8;
    float2 bb[4];
    #pragma unroll
    for (int p = 0; p < 4; ++p) bb[p] = ((const float2*)b1)[c1 / 2 + p];

    for (int tile = blockIdx.x; tile < ntiles; tile += gridDim.x) {
        int row0 = tile * 64;
        __syncthreads();   // prior tile's Ut reads done (also covers Ws load on iter 0)
        const float4* U4 = (const float4*)g_u;
        for (int i = tid; i < 64 * 32; i += 512) {
            int r = i & 63, j = i >> 6;
            float4 v = (row0 + r < n) ? U4[(size_t)(row0 + r) * 32 + j]
                                      : make_float4(0.f, 0.f, 0.f, 0.f);
            int k = 4 * j;
            Ut[(k + 0) * 64 + r] = v.x;
            Ut[(k + 1) * 64 + r] = v.y;
            Ut[(k + 2) * 64 + r] = v.z;
            Ut[(k + 3) * 64 + r] = v.w;
        }
        __syncthreads();

        ull acc[4][4];
        #pragma unroll
        for (int a = 0; a < 4; ++a)
            #pragma unroll
            for (int p = 0; p < 4; ++p) acc[a][p] = 0ull;

        for (int k = 0; k < 128; ++k) {
            float4 xv = *(const float4*)(Ut + k * 64 + r0);
            ull x0 = pk(xv.x, xv.x), x1 = pk(xv.y, xv.y);
            ull x2 = pk(xv.z, xv.z), x3 = pk(xv.w, xv.w);
            const ull* wr = (const ull*)(Ws + k * 256 + c1);
            #pragma unroll
            for (int p = 0; p < 4; ++p) {
                ull wv = wr[p];
                acc[0][p] = f2fma(x0, wv, acc[0][p]);
                acc[1][p] = f2fma(x1, wv, acc[1][p]);
                acc[2][p] = f2fma(x2, wv, acc[2][p]);
                acc[3][p] = f2fma(x3, wv, acc[3][p]);
            }
        }

        #pragma unroll
        for (int rr = 0; rr < 4; ++rr) {
            int row = row0 + r0 + rr;
            if (row >= n) break;
            float2* out = (float2*)(g_y1 + (size_t)row * 256 + c1);
            #pragma unroll
            for (int p = 0; p < 4; ++p) {
                float2 v = upk(acc[rr][p]);
                v.x += bb[p].x; v.y += bb[p].y;
                out[p] = v;
            }
        }
    }
}

// ---------------- K5: persistent GEMM2  out = relu(LN(y1)) @ W2 + b2 + h ----------------
#define SMEMG2 ((32768 + 16384) * 4)
__global__ void __launch_bounds__(512) k_gemm2p(const float4* __restrict__ W2,
                                                const float* __restrict__ b2,
                                                const float* __restrict__ lnw,
                                                const float* __restrict__ lnb,
                                                const float4* __restrict__ h,
                                                float4* __restrict__ out,
                                                int n, int ntiles)
{
    extern __shared__ float sm[];
    float* Ws = sm;             // [256][128]  full W2
    float* Yt = sm + 32768;     // [256][64]   y1^T tile
    __shared__ float s_red[512], s_red2[512];
    __shared__ float s_mean[64], s_scale[64];
    __shared__ float s_lnw[256], s_lnb[256];
    int tid = threadIdx.x;

    for (int i = tid; i < 8192; i += 512)
        ((float4*)Ws)[i] = W2[i];
    if (tid < 256) { s_lnw[tid] = lnw[tid]; s_lnb[tid] = lnb[tid]; }

    int rg = tid & 15, cg = tid >> 4;        // rg in [0,16), cg in [0,32)
    int r0 = rg * 4, c2 = cg * 4;
    float2 bb0 = ((const float2*)b2)[c2 / 2 + 0];
    float2 bb1 = ((const float2*)b2)[c2 / 2 + 1];

    for (int tile = blockIdx.x; tile < ntiles; tile += gridDim.x) {
        int row0 = tile * 64;
        __syncthreads();   // prior tile done (also covers Ws/lnw staging on iter 0)
        const float4* Y4 = (const float4*)g_y1;
        for (int i = tid; i < 64 * 64; i += 512) {
            int r = i & 63, j = i >> 6;
            float4 v = (row0 + r < n) ? Y4[(size_t)(row0 + r) * 64 + j]
                                      : make_float4(0.f, 0.f, 0.f, 0.f);
            int k = 4 * j;
            Yt[(k + 0) * 64 + r] = v.x;
            Yt[(k + 1) * 64 + r] = v.y;
            Yt[(k + 2) * 64 + r] = v.z;
            Yt[(k + 3) * 64 + r] = v.w;
        }
        __syncthreads();

        {   // LN stats: 8 partials x 64 rows
            int r = tid & 63, part = tid >> 6;
            float s = 0.f, s2 = 0.f;
            for (int k = part * 32; k < part * 32 + 32; ++k) {
                float v = Yt[k * 64 + r];
                s += v; s2 = fmaf(v, v, s2);
            }
            s_red[part * 64 + r] = s; s_red2[part * 64 + r] = s2;
        }
        __syncthreads();
        if (tid < 64) {
            float s = 0.f, s2 = 0.f;
            #pragma unroll
            for (int p = 0; p < 8; ++p) { s += s_red[p * 64 + tid]; s2 += s_red2[p * 64 + tid]; }
            float mean = s * (1.f / 256.f);
            float var = fmaxf(s2 * (1.f / 256.f) - mean * mean, 0.f);
            s_mean[tid] = mean;
            s_scale[tid] = rsqrtf(var + 1e-5f);
        }
        __syncthreads();
        for (int i = tid; i < 256 * 64; i += 512) {
            int k = i >> 6, r = i & 63;
            float v = (Yt[i] - s_mean[r]) * s_scale[r] * s_lnw[k] + s_lnb[k];
            Yt[i] = fmaxf(v, 0.f);
        }
        __syncthreads();

        ull acc[4][2];
        #pragma unroll
        for (int a = 0; a < 4; ++a) { acc[a][0] = 0ull; acc[a][1] = 0ull; }

        for (int k = 0; k < 256; ++k) {
            float4 xv = *(const float4*)(Yt + k * 64 + r0);
            ull x0 = pk(xv.x, xv.x), x1 = pk(xv.y, xv.y);
            ull x2 = pk(xv.z, xv.z), x3 = pk(xv.w, xv.w);
            const ull* wr = (const ull*)(Ws + k * 128 + c2);
            ull w0 = wr[0], w1 = wr[1];
            acc[0][0] = f2fma(x0, w0, acc[0][0]);
            acc[0][1] = f2fma(x0, w1, acc[0][1]);
            acc[1][0] = f2fma(x1, w0, acc[1][0]);
            acc[1][1] = f2fma(x1, w1, acc[1][1]);
            acc[2][0] = f2fma(x2, w0, acc[2][0]);
            acc[2][1] = f2fma(x2, w1, acc[2][1]);
            acc[3][0] = f2fma(x3, w0, acc[3][0]);
            acc[3][1] = f2fma(x3, w1, acc[3][1]);
        }

        #pragma unroll
        for (int rr = 0; rr < 4; ++rr) {
            int row = row0 + r0 + rr;
            if (row >= n) break;
            float2 v0 = upk(acc[rr][0]);
            float2 v1 = upk(acc[rr][1]);
            float4 hv = h[(size_t)row * 32 + c2 / 4];
            float4 o;
            o.x = v0.x + bb0.x + hv.x;
            o.y = v0.y + bb0.y + hv.y;
            o.z = v1.x + bb1.x + hv.z;
            o.w = v1.y + bb1.y + hv.w;
            out[(size_t)row * 32 + c2 / 4] = o;
        }
    }
}

// ---------------- launch ----------------
extern "C" void kernel_launch(void* const* d_in, const int* in_sizes, int n_in,
                              void* d_out, int out_size)
{
    const float* h   = (const float*)d_in[0];
    const int*   ei  = (const int*)  d_in[1];
    const float* ea  = (const float*)d_in[2];
    const float* bw  = (const float*)d_in[3];
    const float* bb  = (const float*)d_in[4];
    const float* bm  = (const float*)d_in[5];
    const float* bv  = (const float*)d_in[6];
    const float* tp  = (const float*)d_in[7];
    const float* W1  = (const float*)d_in[8];
    const float* b1  = (const float*)d_in[9];
    const float* lnw = (const float*)d_in[10];
    const float* lnb = (const float*)d_in[11];
    const float* W2  = (const float*)d_in[12];
    const float* b2  = (const float*)d_in[13];

    int n = in_sizes[0] / HF;
    int e = in_sizes[2] / HF;
    const int* src = ei;
    const int* dst = ei + e;
    int ntiles = (n + 63) / 64;

    cudaFuncSetAttribute(k_gemm1p, cudaFuncAttributeMaxDynamicSharedMemorySize, SMEMG1);
    cudaFuncSetAttribute(k_gemm2p, cudaFuncAttributeMaxDynamicSharedMemorySize, SMEMG2);

    int gridp = 152;
    if (gridp > ntiles) gridp = ntiles;

    k_hn_hist<<<(n * HV + 255) / 256, 256>>>((const float4*)h, (const float4*)bw,
                                             (const float4*)bb, (const float4*)bm,
                                             (const float4*)bv, dst, n, e);
    k_scan<<<1, 1024>>>(n);
    k_scatter<<<(e + 255) / 256, 256>>>(src, dst, e);
    k_agg<<<(n + 7) / 8, 256>>>((const float4*)ea, tp, n);      // <- ncu capture lands here
    k_gemm1p<<<gridp, 512, SMEMG1>>>((const float4*)W1, b1, n, ntiles);
    k_gemm2p<<<gridp, 512, SMEMG2>>>((const float4*)W2, b2, lnw, lnb,
                                     (const float4*)h, (float4*)d_out, n, ntiles);
}

// round 6
// speedup vs baseline: 1.9413x; 1.5692x over previous
#include <cuda_runtime.h>
#include <cuda_bf16.h>
#include <cstdint>

#define HF 128
#define HV 32           // float4 per feature row
#define NMAX 50048
#define EMAX 800032

// ---------------- scratch (static device memory; no allocation) ----------------
__device__ float g_hn[NMAX * HF];        // relu(BN(x))
__device__ float g_u [NMAX * HF];        // agg + hn  (MLP input)
__device__ float g_y1[NMAX * 2 * HF];    // GEMM1 output (pre-LN), L2-resident
__device__ int   g_cnt[NMAX];
__device__ int   g_rs [NMAX + 1];
__device__ int   g_cur[NMAX];
__device__ int2  g_edges[EMAX];
// fragment-ordered bf16 weight images (hi / lo splits), 64KB each
__device__ uint2 g_w1h[8192], g_w1l[8192];
__device__ uint2 g_w2h[8192], g_w2l[8192];

// ---------------- helpers ----------------
__device__ __forceinline__ void bfsplit2(float a, float b, uint32_t& hi, uint32_t& lo) {
    __nv_bfloat162 h = __floats2bfloat162_rn(a, b);
    float la = a - __bfloat162float(h.x);
    float lb = b - __bfloat162float(h.y);
    __nv_bfloat162 l = __floats2bfloat162_rn(la, lb);
    hi = *reinterpret_cast<uint32_t*>(&h);
    lo = *reinterpret_cast<uint32_t*>(&l);
}

__device__ __forceinline__ void mma_bf16(float* d, const uint32_t* a, uint32_t b0, uint32_t b1) {
    asm volatile(
        "mma.sync.aligned.m16n8k16.row.col.f32.bf16.bf16.f32 "
        "{%0,%1,%2,%3}, {%4,%5,%6,%7}, {%8,%9}, {%0,%1,%2,%3};"
        : "+f"(d[0]), "+f"(d[1]), "+f"(d[2]), "+f"(d[3])
        : "r"(a[0]), "r"(a[1]), "r"(a[2]), "r"(a[3]), "r"(b0), "r"(b1));
}

// ---------------- K0: hn = relu(BN(h))  +  degree histogram ----------------
__global__ void k_hn_hist(const float4* __restrict__ h,
                          const float4* __restrict__ bw, const float4* __restrict__ bb,
                          const float4* __restrict__ bm, const float4* __restrict__ bv,
                          const int* __restrict__ dst, int n, int e)
{
    int i = blockIdx.x * blockDim.x + threadIdx.x;
    if (i < e) atomicAdd(&g_cnt[dst[i]], 1);
    if (i >= n * HV) return;
    int j = i & (HV - 1);
    float4 x = h[i];
    float4 w = bw[j], b = bb[j], m = bm[j], v = bv[j];
    float4 o;
    o.x = fmaxf((x.x - m.x) * rsqrtf(v.x + 1e-5f) * w.x + b.x, 0.f);
    o.y = fmaxf((x.y - m.y) * rsqrtf(v.y + 1e-5f) * w.y + b.y, 0.f);
    o.z = fmaxf((x.z - m.z) * rsqrtf(v.z + 1e-5f) * w.z + b.z, 0.f);
    o.w = fmaxf((x.w - m.w) * rsqrtf(v.w + 1e-5f) * w.w + b.w, 0.f);
    ((float4*)g_hn)[i] = o;
}

// ---------------- K1: coalesced exclusive scan (single block) ----------------
__global__ void k_scan(int n)
{
    __shared__ int wsum[32];
    __shared__ int s_carry;
    int tid = threadIdx.x, lane = tid & 31, wid = tid >> 5;
    if (tid == 0) s_carry = 0;
    __syncthreads();
    int nIter = (n + 1023) >> 10;
    for (int it = 0; it < nIter; ++it) {
        int idx = (it << 10) + tid;
        int v = (idx < n) ? g_cnt[idx] : 0;
        int x = v;
        #pragma unroll
        for (int o = 1; o < 32; o <<= 1) {
            int u = __shfl_up_sync(0xffffffffu, x, o);
            if (lane >= o) x += u;
        }
        if (lane == 31) wsum[wid] = x;
        __syncthreads();
        if (wid == 0) {
            int w = wsum[lane];
            #pragma unroll
            for (int o = 1; o < 32; o <<= 1) {
                int u = __shfl_up_sync(0xffffffffu, w, o);
                if (lane >= o) w += u;
            }
            wsum[lane] = w;
        }
        __syncthreads();
        int carry = s_carry;
        int excl = x - v + (wid > 0 ? wsum[wid - 1] : 0) + carry;
        if (idx < n) { g_rs[idx] = excl; g_cur[idx] = excl; g_cnt[idx] = 0; }
        __syncthreads();
        if (tid == 0) s_carry = carry + wsum[31];
        __syncthreads();
    }
    if (tid == 0) g_rs[n] = s_carry;
}

// ---------------- K2: scatter edges by dst ----------------
__global__ void k_scatter(const int* __restrict__ src, const int* __restrict__ dst, int e)
{
    int i = blockIdx.x * blockDim.x + threadIdx.x;
    if (i >= e) return;
    int d = dst[i];
    int s = src[i];
    int p = atomicAdd(&g_cur[d], 1);
    g_edges[p] = make_int2(s, i);
}

// ---------------- K3: one-pass softmax aggregation (warp per dst node) ----------------
#define EDGE_ACC(a, hv)                                               \
    {                                                                 \
        float m0 = fmaxf(a.x + hv.x, 0.f) + 1e-7f;                    \
        float m1 = fmaxf(a.y + hv.y, 0.f) + 1e-7f;                    \
        float m2 = fmaxf(a.z + hv.z, 0.f) + 1e-7f;                    \
        float m3 = fmaxf(a.w + hv.w, 0.f) + 1e-7f;                    \
        float e0 = __expf(m0 * t);                                    \
        float e1 = __expf(m1 * t);                                    \
        float e2 = __expf(m2 * t);                                    \
        float e3 = __expf(m3 * t);                                    \
        S.x += e0; P.x = fmaf(m0, e0, P.x);                           \
        S.y += e1; P.y = fmaf(m1, e1, P.y);                           \
        S.z += e2; P.z = fmaf(m2, e2, P.z);                           \
        S.w += e3; P.w = fmaf(m3, e3, P.w);                           \
    }

__global__ void __launch_bounds__(256) k_agg(const float4* __restrict__ ea,
                                             const float* __restrict__ tp, int n)
{
    int warp = (blockIdx.x * blockDim.x + threadIdx.x) >> 5;
    int lane = threadIdx.x & 31;
    if (warp >= n) return;
    float t = __ldg(tp);
    int s0 = g_rs[warp], s1 = g_rs[warp + 1];
    const float4* hn4 = (const float4*)g_hn;
    float4 S = make_float4(0.f, 0.f, 0.f, 0.f);
    float4 P = make_float4(0.f, 0.f, 0.f, 0.f);

    int i = s0;
    for (; i + 4 <= s1; i += 4) {
        int2 q0 = g_edges[i + 0];
        int2 q1 = g_edges[i + 1];
        int2 q2 = g_edges[i + 2];
        int2 q3 = g_edges[i + 3];
        float4 a0 = ea [(size_t)q0.y * HV + lane];
        float4 h0 = hn4[(size_t)q0.x * HV + lane];
        float4 a1 = ea [(size_t)q1.y * HV + lane];
        float4 h1 = hn4[(size_t)q1.x * HV + lane];
        float4 a2 = ea [(size_t)q2.y * HV + lane];
        float4 h2 = hn4[(size_t)q2.x * HV + lane];
        float4 a3 = ea [(size_t)q3.y * HV + lane];
        float4 h3 = hn4[(size_t)q3.x * HV + lane];
        EDGE_ACC(a0, h0);
        EDGE_ACC(a1, h1);
        EDGE_ACC(a2, h2);
        EDGE_ACC(a3, h3);
    }
    for (; i < s1; ++i) {
        int2 q = g_edges[i];
        float4 a  = ea [(size_t)q.y * HV + lane];
        float4 hv = hn4[(size_t)q.x * HV + lane];
        EDGE_ACC(a, hv);
    }

    float4 hd = hn4[warp * HV + lane];
    float4 u;
    u.x = P.x / (S.x + 1e-16f) + hd.x;
    u.y = P.y / (S.y + 1e-16f) + hd.y;
    u.z = P.z / (S.z + 1e-16f) + hd.z;
    u.w = P.w / (S.w + 1e-16f) + hd.w;
    ((float4*)g_u)[warp * HV + lane] = u;
}

// ---------------- K4: prep fragment-ordered bf16 weight images ----------------
// W1: idx = ks(8)*1024 + nb(32)*32 + lane.  W2: idx = ks(16)*512 + nb(16)*32 + lane.
// B frag (16x8 col-major): b0 = rows {k0, k0+1}, b1 = rows {k0+8, k0+9}, col n.
__global__ void k_prepw(const float* __restrict__ W1, const float* __restrict__ W2)
{
    int idx = blockIdx.x * blockDim.x + threadIdx.x;
    if (idx >= 16384) return;
    const float* W;
    uint2 *ih, *il;
    int ks, nb, l, ldn;
    if (idx < 8192) {
        int j = idx;
        ks = j >> 10; nb = (j >> 5) & 31; l = j & 31;
        W = W1; ih = g_w1h; il = g_w1l; ldn = 256;
    } else {
        int j = idx - 8192;
        ks = j >> 9; nb = (j >> 5) & 15; l = j & 31;
        W = W2; ih = g_w2h; il = g_w2l; ldn = 128;
    }
    int k0 = ks * 16 + (l & 3) * 2;
    int nn = nb * 8 + (l >> 2);
    float x00 = W[(size_t)(k0 + 0) * ldn + nn];
    float x01 = W[(size_t)(k0 + 1) * ldn + nn];
    float x10 = W[(size_t)(k0 + 8) * ldn + nn];
    float x11 = W[(size_t)(k0 + 9) * ldn + nn];
    uint32_t b0h, b0l, b1h, b1l;
    bfsplit2(x00, x01, b0h, b0l);
    bfsplit2(x10, x11, b1h, b1l);
    ih[idx & 8191] = make_uint2(b0h, b1h);
    il[idx & 8191] = make_uint2(b0l, b1l);
}

// ---------------- K5: GEMM1 via mma.sync  y1 = u @ W1 + b1 ----------------
// persistent; warp owns 16-row strips; A frags LDG direct from g_u (L2).
#define SMEM_MMA1 (131072 + 1024)
__global__ void __launch_bounds__(256, 1) k_mma1(const float* __restrict__ b1,
                                                 int n, int nstrips)
{
    extern __shared__ char smem[];
    uint2* sWh  = (uint2*)smem;             // 8192
    uint2* sWl  = (uint2*)(smem + 65536);   // 8192
    float* s_b1 = (float*)(smem + 131072);  // 256
    int tid = threadIdx.x, wid = tid >> 5, lane = tid & 31;
    for (int i = tid; i < 8192; i += 256) { sWh[i] = g_w1h[i]; sWl[i] = g_w1l[i]; }
    if (tid < 256) s_b1[tid] = b1[tid];
    __syncthreads();

    int g = lane >> 2, t = lane & 3;
    int nwarps = gridDim.x * 8;
    for (int strip = blockIdx.x * 8 + wid; strip < nstrips; strip += nwarps) {
        int rg0 = strip * 16 + g;
        int rg1 = rg0 + 8;
        const float* up0 = g_u + (size_t)rg0 * 128;
        const float* up1 = g_u + (size_t)rg1 * 128;
        #pragma unroll
        for (int nh = 0; nh < 2; ++nh) {          // 256 output cols in 2 halves
            float acc[16][4];
            #pragma unroll
            for (int nb = 0; nb < 16; ++nb) {
                acc[nb][0] = 0.f; acc[nb][1] = 0.f; acc[nb][2] = 0.f; acc[nb][3] = 0.f;
            }
            for (int ks = 0; ks < 8; ++ks) {
                int k0 = ks * 16 + t * 2;
                float2 v00 = *(const float2*)(up0 + k0);
                float2 v01 = *(const float2*)(up0 + k0 + 8);
                float2 v10 = *(const float2*)(up1 + k0);
                float2 v11 = *(const float2*)(up1 + k0 + 8);
                uint32_t ah[4], al[4];
                bfsplit2(v00.x, v00.y, ah[0], al[0]);
                bfsplit2(v10.x, v10.y, ah[1], al[1]);
                bfsplit2(v01.x, v01.y, ah[2], al[2]);
                bfsplit2(v11.x, v11.y, ah[3], al[3]);
                const uint2* wh = sWh + (ks * 32 + nh * 16) * 32 + lane;
                const uint2* wl = sWl + (ks * 32 + nh * 16) * 32 + lane;
                #pragma unroll
                for (int nb = 0; nb < 16; ++nb) {
                    uint2 bh = wh[nb * 32];
                    uint2 bl = wl[nb * 32];
                    mma_bf16(acc[nb], ah, bh.x, bh.y);
                    mma_bf16(acc[nb], ah, bl.x, bl.y);
                    mma_bf16(acc[nb], al, bh.x, bh.y);
                }
            }
            #pragma unroll
            for (int nb = 0; nb < 16; ++nb) {
                int col = nh * 128 + nb * 8 + t * 2;
                float2 bb = *(const float2*)(s_b1 + col);
                if (rg0 < n)
                    *(float2*)(g_y1 + (size_t)rg0 * 256 + col) =
                        make_float2(acc[nb][0] + bb.x, acc[nb][1] + bb.y);
                if (rg1 < n)
                    *(float2*)(g_y1 + (size_t)rg1 * 256 + col) =
                        make_float2(acc[nb][2] + bb.x, acc[nb][3] + bb.y);
            }
        }
    }
}

// ---------------- K6: GEMM2 via mma.sync  out = relu(LN(y1)) @ W2 + b2 + h ----------------
#define SMEM_MMA2 (131072 + 2560)
__global__ void __launch_bounds__(256, 1) k_mma2(const float* __restrict__ b2,
                                                 const float* __restrict__ lnw,
                                                 const float* __restrict__ lnb,
                                                 const float* __restrict__ hres,
                                                 float* __restrict__ out,
                                                 int n, int nstrips)
{
    extern __shared__ char smem[];
    uint2* sWh   = (uint2*)smem;
    uint2* sWl   = (uint2*)(smem + 65536);
    float* s_lnw = (float*)(smem + 131072);          // 256
    float* s_lnb = (float*)(smem + 131072 + 1024);   // 256
    float* s_b2  = (float*)(smem + 131072 + 2048);   // 128
    int tid = threadIdx.x, wid = tid >> 5, lane = tid & 31;
    for (int i = tid; i < 8192; i += 256) { sWh[i] = g_w2h[i]; sWl[i] = g_w2l[i]; }
    if (tid < 256) { s_lnw[tid] = lnw[tid]; s_lnb[tid] = lnb[tid]; }
    if (tid < 128) s_b2[tid] = b2[tid];
    __syncthreads();

    int g = lane >> 2, t = lane & 3;
    int nwarps = gridDim.x * 8;
    for (int strip = blockIdx.x * 8 + wid; strip < nstrips; strip += nwarps) {
        // ---- LN stats for the 16 rows of this strip ----
        float meanA = 0.f, scaleA = 0.f, meanB = 0.f, scaleB = 0.f;
        #pragma unroll
        for (int r = 0; r < 16; ++r) {
            int grow = strip * 16 + r;
            const float4* yp = (const float4*)(g_y1 + (size_t)grow * 256);
            float4 a = yp[lane * 2], b = yp[lane * 2 + 1];
            float s  = a.x + a.y + a.z + a.w + b.x + b.y + b.z + b.w;
            float s2 = a.x*a.x + a.y*a.y + a.z*a.z + a.w*a.w
                     + b.x*b.x + b.y*b.y + b.z*b.z + b.w*b.w;
            #pragma unroll
            for (int o = 16; o > 0; o >>= 1) {
                s  += __shfl_xor_sync(0xffffffffu, s, o);
                s2 += __shfl_xor_sync(0xffffffffu, s2, o);
            }
            float mean = s * (1.f / 256.f);
            float var = fmaxf(s2 * (1.f / 256.f) - mean * mean, 0.f);
            float sc = rsqrtf(var + 1e-5f);
            if (r == g)     { meanA = mean; scaleA = sc; }
            if (r == g + 8) { meanB = mean; scaleB = sc; }
        }

        int rg0 = strip * 16 + g, rg1 = rg0 + 8;
        const float* yp0 = g_y1 + (size_t)rg0 * 256;
        const float* yp1 = g_y1 + (size_t)rg1 * 256;
        float acc[16][4];
        #pragma unroll
        for (int nb = 0; nb < 16; ++nb) {
            acc[nb][0] = 0.f; acc[nb][1] = 0.f; acc[nb][2] = 0.f; acc[nb][3] = 0.f;
        }
        for (int ks = 0; ks < 16; ++ks) {
            int k0 = ks * 16 + t * 2;
            float2 v00 = *(const float2*)(yp0 + k0);
            float2 v01 = *(const float2*)(yp0 + k0 + 8);
            float2 v10 = *(const float2*)(yp1 + k0);
            float2 v11 = *(const float2*)(yp1 + k0 + 8);
            float2 w0 = *(const float2*)(s_lnw + k0);
            float2 w1 = *(const float2*)(s_lnw + k0 + 8);
            float2 z0 = *(const float2*)(s_lnb + k0);
            float2 z1 = *(const float2*)(s_lnb + k0 + 8);
            float x00 = fmaxf((v00.x - meanA) * scaleA * w0.x + z0.x, 0.f);
            float x01 = fmaxf((v00.y - meanA) * scaleA * w0.y + z0.y, 0.f);
            float x02 = fmaxf((v01.x - meanA) * scaleA * w1.x + z1.x, 0.f);
            float x03 = fmaxf((v01.y - meanA) * scaleA * w1.y + z1.y, 0.f);
            float x10 = fmaxf((v10.x - meanB) * scaleB * w0.x + z0.x, 0.f);
            float x11 = fmaxf((v10.y - meanB) * scaleB * w0.y + z0.y, 0.f);
            float x12 = fmaxf((v11.x - meanB) * scaleB * w1.x + z1.x, 0.f);
            float x13 = fmaxf((v11.y - meanB) * scaleB * w1.y + z1.y, 0.f);
            uint32_t ah[4], al[4];
            bfsplit2(x00, x01, ah[0], al[0]);
            bfsplit2(x10, x11, ah[1], al[1]);
            bfsplit2(x02, x03, ah[2], al[2]);
            bfsplit2(x12, x13, ah[3], al[3]);
            const uint2* wh = sWh + ks * 16 * 32 + lane;
            const uint2* wl = sWl + ks * 16 * 32 + lane;
            #pragma unroll
            for (int nb = 0; nb < 16; ++nb) {
                uint2 bh = wh[nb * 32];
                uint2 bl = wl[nb * 32];
                mma_bf16(acc[nb], ah, bh.x, bh.y);
                mma_bf16(acc[nb], ah, bl.x, bl.y);
                mma_bf16(acc[nb], al, bh.x, bh.y);
            }
        }
        #pragma unroll
        for (int nb = 0; nb < 16; ++nb) {
            int col = nb * 8 + t * 2;
            float2 bb = *(const float2*)(s_b2 + col);
            if (rg0 < n) {
                float2 hv = *(const float2*)(hres + (size_t)rg0 * 128 + col);
                *(float2*)(out + (size_t)rg0 * 128 + col) =
                    make_float2(acc[nb][0] + bb.x + hv.x, acc[nb][1] + bb.y + hv.y);
            }
            if (rg1 < n) {
                float2 hv = *(const float2*)(hres + (size_t)rg1 * 128 + col);
                *(float2*)(out + (size_t)rg1 * 128 + col) =
                    make_float2(acc[nb][2] + bb.x + hv.x, acc[nb][3] + bb.y + hv.y);
            }
        }
    }
}

// ---------------- launch ----------------
extern "C" void kernel_launch(void* const* d_in, const int* in_sizes, int n_in,
                              void* d_out, int out_size)
{
    const float* h   = (const float*)d_in[0];
    const int*   ei  = (const int*)  d_in[1];
    const float* ea  = (const float*)d_in[2];
    const float* bw  = (const float*)d_in[3];
    const float* bb  = (const float*)d_in[4];
    const float* bm  = (const float*)d_in[5];
    const float* bv  = (const float*)d_in[6];
    const float* tp  = (const float*)d_in[7];
    const float* W1  = (const float*)d_in[8];
    const float* b1  = (const float*)d_in[9];
    const float* lnw = (const float*)d_in[10];
    const float* lnb = (const float*)d_in[11];
    const float* W2  = (const float*)d_in[12];
    const float* b2  = (const float*)d_in[13];

    int n = in_sizes[0] / HF;
    int e = in_sizes[2] / HF;
    const int* src = ei;
    const int* dst = ei + e;
    int nstrips = (n + 15) / 16;

    cudaFuncSetAttribute(k_mma1, cudaFuncAttributeMaxDynamicSharedMemorySize, SMEM_MMA1);
    cudaFuncSetAttribute(k_mma2, cudaFuncAttributeMaxDynamicSharedMemorySize, SMEM_MMA2);

    int gridp = 152;

    k_hn_hist<<<(n * HV + 255) / 256, 256>>>((const float4*)h, (const float4*)bw,
                                             (const float4*)bb, (const float4*)bm,
                                             (const float4*)bv, dst, n, e);
    k_scan<<<1, 1024>>>(n);
    k_scatter<<<(e + 255) / 256, 256>>>(src, dst, e);
    k_agg<<<(n + 7) / 8, 256>>>((const float4*)ea, tp, n);      // <- ncu capture lands here
    k_prepw<<<64, 256>>>(W1, W2);
    k_mma1<<<gridp, 256, SMEM_MMA1>>>(b1, n, nstrips);
    k_mma2<<<gridp, 256, SMEM_MMA2>>>(b2, lnw, lnb, h, (float*)d_out, n, nstrips);
}